// round 1
// baseline (speedup 1.0000x reference)
#include <cuda_runtime.h>
#include <cuda_bf16.h>
#include <cstdint>

// Problem constants (fixed by the dataset): B=2, N=250000, C=32, S=128
#define NPTS   250000
#define NBATCH 2
#define MTOT   (NPTS * NBATCH)        // 500000
#define CDIM   32
#define SDIM   128
#define GRID_CELLS (NBATCH * SDIM * SDIM * SDIM)  // 4,194,304

// Scratch: hash grid + two intermediate feature buffers (no cudaMalloc allowed)
__device__ int   g_grid[GRID_CELLS];
__device__ float g_feat1[MTOT * CDIM];
__device__ float g_feat2[MTOT * CDIM];

// ---------------------------------------------------------------------------
// Kernel 1: init grid to -1 (vectorized int4)
// ---------------------------------------------------------------------------
__global__ void init_grid_kernel() {
    int i = blockIdx.x * blockDim.x + threadIdx.x;
    int4* g = reinterpret_cast<int4*>(g_grid);
    if (i < GRID_CELLS / 4) {
        g[i] = make_int4(-1, -1, -1, -1);
    }
}

// ---------------------------------------------------------------------------
// Kernel 2: scatter point index into grid
// coordinates: (B, N, 3) int32, unique cells per batch (no collisions)
// ---------------------------------------------------------------------------
__global__ void scatter_kernel(const int* __restrict__ coords) {
    int m = blockIdx.x * blockDim.x + threadIdx.x;
    if (m >= MTOT) return;
    int b = (m >= NPTS) ? 1 : 0;
    int x = coords[3 * m + 0];
    int y = coords[3 * m + 1];
    int z = coords[3 * m + 2];
    g_grid[((b * SDIM + x) * SDIM + y) * SDIM + z] = m;
}

// ---------------------------------------------------------------------------
// Kernel 3: submanifold sparse conv layer.
// One warp per output point; lane = output channel.
// For each of 27 offsets: uniform grid lookup; if a neighbor exists, each
// lane loads its slice of the 32-float feature vector (coalesced), then the
// warp does 32 FMAs with SHFL broadcast of f[cin] and W read through L1.
// W layout: [dx][dy][dz][cin][cout] -> k*1024 + cin*32 + cout
// ---------------------------------------------------------------------------
__global__ __launch_bounds__(256, 8)
void subm_conv_kernel(const float* __restrict__ in,
                      float*       __restrict__ out,
                      const float* __restrict__ W,
                      const int*   __restrict__ coords,
                      int relu)
{
    int warp_global = (blockIdx.x * blockDim.x + threadIdx.x) >> 5;
    int lane = threadIdx.x & 31;
    if (warp_global >= MTOT) return;

    const int m = warp_global;
    const int b = (m >= NPTS) ? 1 : 0;
    const int cx = coords[3 * m + 0];
    const int cy = coords[3 * m + 1];
    const int cz = coords[3 * m + 2];

    const int* gbase = g_grid + b * (SDIM * SDIM * SDIM);

    float acc = 0.0f;

    #pragma unroll 1
    for (int k = 0; k < 27; ++k) {
        const int dx = k / 9;
        const int r  = k - dx * 9;
        const int dy = r / 3;
        const int dz = r - dy * 3;

        const int nx = cx + dx - 1;
        const int ny = cy + dy - 1;
        const int nz = cz + dz - 1;
        if ((unsigned)nx >= SDIM || (unsigned)ny >= SDIM || (unsigned)nz >= SDIM)
            continue;                                  // uniform across warp

        const int idx = __ldg(gbase + ((nx * SDIM + ny) * SDIM + nz));
        if (idx < 0) continue;                         // uniform across warp

        // Coalesced 128B gather of the neighbor's feature vector
        const float fv = __ldg(in + idx * CDIM + lane);
        const float* wk = W + k * (CDIM * CDIM);

        #pragma unroll
        for (int cin = 0; cin < CDIM; ++cin) {
            const float v = __shfl_sync(0xffffffffu, fv, cin);
            acc = fmaf(v, __ldg(wk + cin * CDIM + lane), acc);
        }
    }

    if (relu) acc = fmaxf(acc, 0.0f);
    out[m * CDIM + lane] = acc;
}

// ---------------------------------------------------------------------------
// Launch: resolve inputs by element count (robust to batch_size scalar
// being materialized or not):
//   features:   16,000,000 f32
//   coordinates: 1,500,000 i32
//   W1, W2, W3:     27,648 f32 each (in dict order)
// ---------------------------------------------------------------------------
extern "C" void kernel_launch(void* const* d_in, const int* in_sizes, int n_in,
                              void* d_out, int out_size)
{
    const float* features = nullptr;
    const int*   coords   = nullptr;
    const float* Ws[3]    = {nullptr, nullptr, nullptr};
    int wcount = 0;

    for (int i = 0; i < n_in; ++i) {
        if (in_sizes[i] == MTOT * CDIM && features == nullptr) {
            features = (const float*)d_in[i];
        } else if (in_sizes[i] == MTOT * 3 && coords == nullptr) {
            coords = (const int*)d_in[i];
        } else if (in_sizes[i] == 27 * CDIM * CDIM && wcount < 3) {
            Ws[wcount++] = (const float*)d_in[i];
        }
    }

    float* x1 = nullptr;
    float* x2 = nullptr;
    cudaGetSymbolAddress((void**)&x1, g_feat1);
    cudaGetSymbolAddress((void**)&x2, g_feat2);

    float* out = (float*)d_out;

    // 1) grid init
    {
        int n = GRID_CELLS / 4;
        init_grid_kernel<<<(n + 255) / 256, 256>>>();
    }
    // 2) scatter
    scatter_kernel<<<(MTOT + 255) / 256, 256>>>(coords);

    // 3) three conv layers (warp per point)
    const int threads = 256;
    const int warps_per_block = threads / 32;
    const int blocks = (MTOT + warps_per_block - 1) / warps_per_block;

    subm_conv_kernel<<<blocks, threads>>>(features, x1, Ws[0], coords, 1);
    subm_conv_kernel<<<blocks, threads>>>(x1,       x2, Ws[1], coords, 1);
    subm_conv_kernel<<<blocks, threads>>>(x2,      out, Ws[2], coords, 0);
}

// round 2
// speedup vs baseline: 2.6061x; 2.6061x over previous
#include <cuda_runtime.h>
#include <cuda_bf16.h>
#include <cstdint>

// Problem constants (fixed by the dataset): B=2, N=250000, C=32, S=128
#define NPTS   250000
#define NBATCH 2
#define MTOT   (NPTS * NBATCH)        // 500000
#define CDIM   32
#define SDIM   128
#define GRID_CELLS (NBATCH * SDIM * SDIM * SDIM)  // 4,194,304

#define SLOTS    1024                 // grid slots scanned per gemm block
#define GTHREADS 256                  // threads per gemm block (8 warps)

// Scratch (no cudaMalloc allowed): hash grid, neighbor table, intermediates
__device__ int   g_grid[GRID_CELLS];
__device__ int   g_nbr[27 * MTOT];           // 54 MB, built once, reused x3
__device__ float g_x1[MTOT * CDIM];
__device__ float g_x2[MTOT * CDIM];

// ---------------------------------------------------------------------------
// packed f32x2 helpers (Blackwell dual-rate fp32)
// ---------------------------------------------------------------------------
__device__ __forceinline__ unsigned long long pack2(float lo, float hi) {
    unsigned long long r;
    asm("mov.b64 %0, {%1, %2};" : "=l"(r) : "f"(lo), "f"(hi));
    return r;
}
__device__ __forceinline__ void unpack2(unsigned long long v, float& lo, float& hi) {
    asm("mov.b64 {%0, %1}, %2;" : "=f"(lo), "=f"(hi) : "l"(v));
}
__device__ __forceinline__ void ffma2(unsigned long long& d,
                                      unsigned long long a,
                                      unsigned long long b) {
    asm("fma.rn.f32x2 %0, %1, %2, %0;" : "+l"(d) : "l"(a), "l"(b));
}

// ---------------------------------------------------------------------------
// init grid to -1
// ---------------------------------------------------------------------------
__global__ void init_grid_kernel() {
    int i = blockIdx.x * blockDim.x + threadIdx.x;
    if (i < GRID_CELLS / 4) {
        reinterpret_cast<int4*>(g_grid)[i] = make_int4(-1, -1, -1, -1);
    }
}

// ---------------------------------------------------------------------------
// scatter point index into grid
// ---------------------------------------------------------------------------
__global__ void scatter_kernel(const int* __restrict__ coords) {
    int m = blockIdx.x * blockDim.x + threadIdx.x;
    if (m >= MTOT) return;
    int b = (m >= NPTS) ? 1 : 0;
    int x = coords[3 * m + 0];
    int y = coords[3 * m + 1];
    int z = coords[3 * m + 2];
    g_grid[((b * SDIM + x) * SDIM + y) * SDIM + z] = m;
}

// ---------------------------------------------------------------------------
// build neighbor table: g_nbr[k][m] = input index at offset k, or -1
// grid: (ceil(MTOT/256), 27)
// ---------------------------------------------------------------------------
__global__ void build_nbr_kernel(const int* __restrict__ coords) {
    int m = blockIdx.x * blockDim.x + threadIdx.x;
    int k = blockIdx.y;
    if (m >= MTOT) return;
    int b = (m >= NPTS) ? 1 : 0;
    int dx = k / 9 - 1;
    int dy = (k / 3) % 3 - 1;
    int dz = k % 3 - 1;
    int nx = coords[3 * m + 0] + dx;
    int ny = coords[3 * m + 1] + dy;
    int nz = coords[3 * m + 2] + dz;
    int idx = -1;
    if ((unsigned)nx < SDIM && (unsigned)ny < SDIM && (unsigned)nz < SDIM)
        idx = g_grid[((b * SDIM + nx) * SDIM + ny) * SDIM + nz];
    g_nbr[k * MTOT + m] = idx;
}

// ---------------------------------------------------------------------------
// zero a float buffer (float4 stores)
// ---------------------------------------------------------------------------
__global__ void zero_kernel(float* __restrict__ p, int n4) {
    int i = blockIdx.x * blockDim.x + threadIdx.x;
    if (i < n4) reinterpret_cast<float4*>(p)[i] = make_float4(0.f, 0.f, 0.f, 0.f);
}

// ---------------------------------------------------------------------------
// gather-GEMM-scatter for one layer.
// grid: (ceil(MTOT/SLOTS), 27). Block: 256 threads = 8 warps.
// Block (cx, k): scans nbr[k][cx*SLOTS .. +SLOTS), compacts valid (in,out)
// pairs, stages W[k] (32x32) in smem, then thread-per-pair GEMM:
//   thread gathers its own 32-float input row (optionally ReLU'd),
//   accumulates 32 couts as 16 packed f32x2, W broadcast from smem.
// Scatter: per-warp smem transpose, then row-coalesced atomicAdd (REDG).
// ---------------------------------------------------------------------------
__global__ __launch_bounds__(GTHREADS)
void spconv_gemm_kernel(const float* __restrict__ in,
                        float*       __restrict__ out,
                        const float* __restrict__ W,
                        int relu_in)
{
    __shared__ float s_W[CDIM * CDIM];          // 4 KB
    __shared__ int   s_in[SLOTS];               // 4 KB
    __shared__ int   s_om[SLOTS];               // 4 KB
    __shared__ float s_tr[8][32 * 33];          // 33 KB transpose tiles
    __shared__ int   s_cnt;

    const int tid  = threadIdx.x;
    const int lane = tid & 31;
    const int wid  = tid >> 5;
    const int k    = blockIdx.y;
    const int base = blockIdx.x * SLOTS;

    if (tid == 0) s_cnt = 0;
    for (int i = tid; i < CDIM * CDIM; i += GTHREADS)
        s_W[i] = W[k * (CDIM * CDIM) + i];
    __syncthreads();

    // --- compact valid pairs (warp-aggregated) ---
    const int* nb = g_nbr + (long long)k * MTOT;
    for (int s = tid; s < SLOTS; s += GTHREADS) {   // exactly 4 full iterations
        int m = base + s;
        int v = (m < MTOT) ? __ldg(nb + m) : -1;
        unsigned bal = __ballot_sync(0xffffffffu, v >= 0);
        int cnt = __popc(bal);
        int bpos = 0;
        if (lane == 0 && cnt) bpos = atomicAdd(&s_cnt, cnt);
        bpos = __shfl_sync(0xffffffffu, bpos, 0);
        if (v >= 0) {
            int r = __popc(bal & ((1u << lane) - 1));
            s_in[bpos + r] = v;
            s_om[bpos + r] = m;
        }
    }
    __syncthreads();
    const int V = s_cnt;

    // --- GEMM over compacted pairs, 32 pairs per warp-group ---
    for (int g0 = wid * 32; g0 < V; g0 += 8 * 32) {
        int p = g0 + lane;
        int in_idx = (p < V) ? s_in[p] : 0;

        // gather this pair's feature row (32 floats)
        const float4* fp = reinterpret_cast<const float4*>(in + (long long)in_idx * CDIM);
        float fr[32];
        #pragma unroll
        for (int j = 0; j < 8; j++) {
            float4 q = __ldg(fp + j);
            if (relu_in) {
                q.x = fmaxf(q.x, 0.f); q.y = fmaxf(q.y, 0.f);
                q.z = fmaxf(q.z, 0.f); q.w = fmaxf(q.w, 0.f);
            }
            fr[4 * j + 0] = q.x; fr[4 * j + 1] = q.y;
            fr[4 * j + 2] = q.z; fr[4 * j + 3] = q.w;
        }

        unsigned long long acc[16];
        #pragma unroll
        for (int i = 0; i < 16; i++) acc[i] = 0ull;

        #pragma unroll
        for (int c = 0; c < 32; c++) {
            unsigned long long fv2 = pack2(fr[c], fr[c]);
            const ulonglong2* wr =
                reinterpret_cast<const ulonglong2*>(s_W + c * 32);
            #pragma unroll
            for (int j = 0; j < 8; j++) {
                ulonglong2 q = wr[j];                 // LDS.128 broadcast
                ffma2(acc[2 * j + 0], fv2, q.x);      // couts 4j, 4j+1
                ffma2(acc[2 * j + 1], fv2, q.y);      // couts 4j+2, 4j+3
            }
        }

        // transpose: s_tr[wid][cout][pair_lane]
        float* tp = s_tr[wid];
        #pragma unroll
        for (int i = 0; i < 16; i++) {
            float lo, hi;
            unpack2(acc[i], lo, hi);
            tp[(2 * i + 0) * 33 + lane] = lo;
            tp[(2 * i + 1) * 33 + lane] = hi;
        }
        __syncwarp();

        // scatter: lanes = couts of one pair row, coalesced 128B atomics
        int nv = min(32, V - g0);
        for (int j = 0; j < nv; j++) {
            int mo = s_om[g0 + j];
            atomicAdd(out + (long long)mo * CDIM + lane, tp[lane * 33 + j]);
        }
        __syncwarp();
    }
}

// ---------------------------------------------------------------------------
// launch
// ---------------------------------------------------------------------------
extern "C" void kernel_launch(void* const* d_in, const int* in_sizes, int n_in,
                              void* d_out, int out_size)
{
    const float* features = nullptr;
    const int*   coords   = nullptr;
    const float* Ws[3]    = {nullptr, nullptr, nullptr};
    int wcount = 0;

    for (int i = 0; i < n_in; ++i) {
        if (in_sizes[i] == MTOT * CDIM && features == nullptr) {
            features = (const float*)d_in[i];
        } else if (in_sizes[i] == MTOT * 3 && coords == nullptr) {
            coords = (const int*)d_in[i];
        } else if (in_sizes[i] == 27 * CDIM * CDIM && wcount < 3) {
            Ws[wcount++] = (const float*)d_in[i];
        }
    }

    float* x1 = nullptr;
    float* x2 = nullptr;
    cudaGetSymbolAddress((void**)&x1, g_x1);
    cudaGetSymbolAddress((void**)&x2, g_x2);
    float* out = (float*)d_out;

    // 1) grid init + scatter + neighbor table (shared across all 3 layers)
    init_grid_kernel<<<(GRID_CELLS / 4 + 255) / 256, 256>>>();
    scatter_kernel<<<(MTOT + 255) / 256, 256>>>(coords);
    {
        dim3 g((MTOT + 255) / 256, 27);
        build_nbr_kernel<<<g, 256>>>(coords);
    }

    // 2) zero accumulation buffers (d_out is poisoned by the harness)
    const int n4 = MTOT * CDIM / 4;
    zero_kernel<<<(n4 + 255) / 256, 256>>>(x1, n4);
    zero_kernel<<<(n4 + 255) / 256, 256>>>(x2, n4);
    zero_kernel<<<(n4 + 255) / 256, 256>>>(out, n4);

    // 3) three layers of gather-GEMM-scatter
    dim3 gg((MTOT + SLOTS - 1) / SLOTS, 27);
    spconv_gemm_kernel<<<gg, GTHREADS>>>(features, x1, Ws[0], 0);
    spconv_gemm_kernel<<<gg, GTHREADS>>>(x1,       x2, Ws[1], 1);
    spconv_gemm_kernel<<<gg, GTHREADS>>>(x2,      out, Ws[2], 1);
}